// round 15
// baseline (speedup 1.0000x reference)
#include <cuda_runtime.h>
#include <cuda_fp16.h>
#include <cstdint>
#include <math.h>

// Problem constants
#define TT 512
#define BB 64
#define II 300
#define HH 1000
#define G4 4000
#define KP 1024           // padded K
#define NBLK 125          // persistent blocks (<=148 SMs -> co-resident)

// ---------------------------------------------------------------------------
// Device scratch (allocation-free: __device__ globals)
// ---------------------------------------------------------------------------
__device__ float g_xg[(size_t)TT * BB * G4];   // x_gates [T,B,4H]
__device__ __half g_hf[2][BB * KP];            // h as fp16 MMA fragments, 2 parities
__device__ unsigned g_slot[128];               // per-block step slots

// ---------------------------------------------------------------------------
// helpers
// ---------------------------------------------------------------------------
__device__ __forceinline__ unsigned f2tf32(float x) {
    unsigned y;
    asm("cvt.rna.tf32.f32 %0, %1;" : "=r"(y) : "f"(x));
    return y;
}
__device__ __forceinline__ void mma_tf32(float c[4], unsigned a0, unsigned a1,
                                         unsigned a2, unsigned a3,
                                         unsigned b0, unsigned b1) {
    asm volatile(
        "mma.sync.aligned.m16n8k8.row.col.f32.tf32.tf32.f32 "
        "{%0,%1,%2,%3}, {%4,%5,%6,%7}, {%8,%9}, {%0,%1,%2,%3};"
        : "+f"(c[0]), "+f"(c[1]), "+f"(c[2]), "+f"(c[3])
        : "r"(a0), "r"(a1), "r"(a2), "r"(a3), "r"(b0), "r"(b1));
}
__device__ __forceinline__ void mma_f16(float c[4], unsigned a0, unsigned a1,
                                        unsigned a2, unsigned a3,
                                        unsigned b0, unsigned b1) {
    asm volatile(
        "mma.sync.aligned.m16n8k16.row.col.f32.f16.f16.f32 "
        "{%0,%1,%2,%3}, {%4,%5,%6,%7}, {%8,%9}, {%0,%1,%2,%3};"
        : "+f"(c[0]), "+f"(c[1]), "+f"(c[2]), "+f"(c[3])
        : "r"(a0), "r"(a1), "r"(a2), "r"(a3), "r"(b0), "r"(b1));
}
__device__ __forceinline__ float sigmoidf_(float x) { return 1.0f / (1.0f + __expf(-x)); }
__device__ __forceinline__ float tanhf_(float x) { return 2.0f / (1.0f + __expf(-2.0f * x)) - 1.0f; }

__device__ __forceinline__ unsigned ld_acq(const unsigned* p) {
    unsigned v;
    asm volatile("ld.acquire.gpu.global.u32 %0, [%1];" : "=r"(v) : "l"(p) : "memory");
    return v;
}
__device__ __forceinline__ void st_rel(unsigned* p, unsigned v) {
    asm volatile("st.release.gpu.global.u32 [%0], %1;" :: "l"(p), "r"(v) : "memory");
}

// fp16 fragment half-index of A element (b, kglob) for m16n8k16.row:
//   a0:(g,2t/2t+1) a1:(g+8,..) a2:(g,2t+8/9) a3:(g+8,..), lane = g*4 + t
__device__ __forceinline__ int frag_half_of(int b, int kglob) {
    int wm = b >> 5, mt = (b >> 4) & 1, r = b & 15, g = r & 7, rsel = r >> 3;
    int ch = kglob >> 7, kr = kglob & 127;
    int wk = kr >> 4, kl = kr & 15;
    int p = kl >> 1, lo = kl & 1, tq = p & 3, ksel = p >> 2;
    int lane = g * 4 + tq;
    int reg  = ksel * 2 + rsel;
    int word = ((((wm * 8 + wk) * 8 + ch) * 2 + mt) * 32 + lane) * 4 + reg;
    return word * 2 + lo;
}

// ---------------------------------------------------------------------------
// Kernel 1: x_gates GEMM (tf32)  +  prep row (y==512):
//           h0 -> g_hf[0] fp16 fragments, slot reset.
// ---------------------------------------------------------------------------
__global__ void __launch_bounds__(256) xgates_kernel(
    const float* __restrict__ X, const float* __restrict__ Wih,
    const float* __restrict__ b_ih, const float* __restrict__ b_hh,
    const float* __restrict__ h0)
{
    if (blockIdx.y == 512) {               // prep row: 63 blocks
        const int bx = blockIdx.x;
        if (bx == 0 && threadIdx.x < 128) g_slot[threadIdx.x] = 0u;
        for (int b = bx; b < BB; b += 63) {
            for (int k = threadIdx.x; k < HH; k += 256)
                g_hf[0][frag_half_of(b, k)] = __float2half_rn(h0[b * HH + k]);
        }
        return;
    }

    const int m0 = blockIdx.y * 64;
    const int n0 = blockIdx.x * 64;
    const int tid  = threadIdx.x;
    const int lane = tid & 31;
    const int warp = tid >> 5;
    const int wm = warp & 3;
    const int wn = warp >> 2;

    __shared__ unsigned a_s[64][17];
    __shared__ unsigned b_s[64][17];

    float acc[4][4];
#pragma unroll
    for (int s = 0; s < 4; ++s)
#pragma unroll
        for (int i = 0; i < 4; ++i) acc[s][i] = 0.0f;

    const int g_id = lane >> 2;
    const int t_id = lane & 3;

    for (int ch = 0; ch < 19; ++ch) {
        const int k0 = ch * 16;
#pragma unroll
        for (int it = 0; it < 4; ++it) {
            int i = tid + it * 256;
            int m = i >> 4, k = i & 15;
            float va = (k0 + k < II) ? X[(size_t)(m0 + m) * II + k0 + k] : 0.0f;
            a_s[m][k] = f2tf32(va);
            int r = n0 + m;
            float vb = (r < G4 && k0 + k < II) ? Wih[(size_t)r * II + k0 + k] : 0.0f;
            b_s[m][k] = f2tf32(vb);
        }
        __syncthreads();

#pragma unroll
        for (int kk = 0; kk < 2; ++kk) {
            const int kb = kk * 8;
            unsigned a[4];
            a[0] = a_s[wm * 16 + g_id][kb + t_id];
            a[1] = a_s[wm * 16 + g_id + 8][kb + t_id];
            a[2] = a_s[wm * 16 + g_id][kb + t_id + 4];
            a[3] = a_s[wm * 16 + g_id + 8][kb + t_id + 4];
#pragma unroll
            for (int s = 0; s < 4; ++s) {
                unsigned b0 = b_s[wn * 32 + s * 8 + g_id][kb + t_id];
                unsigned b1 = b_s[wn * 32 + s * 8 + g_id][kb + t_id + 4];
                mma_tf32(acc[s], a[0], a[1], a[2], a[3], b0, b1);
            }
        }
        __syncthreads();
    }

#pragma unroll
    for (int s = 0; s < 4; ++s) {
        int n = n0 + wn * 32 + s * 8 + 2 * t_id;
        int row = m0 + wm * 16 + g_id;
        if (n < G4) {
            float bia0 = b_ih[n] + b_hh[n];
            float bia1 = b_ih[n + 1] + b_hh[n + 1];
            g_xg[(size_t)row * G4 + n]           = acc[s][0] + bia0;
            g_xg[(size_t)row * G4 + n + 1]       = acc[s][1] + bia1;
            g_xg[(size_t)(row + 8) * G4 + n]     = acc[s][2] + bia0;
            g_xg[(size_t)(row + 8) * G4 + n + 1] = acc[s][3] + bia1;
        }
    }
}

// ---------------------------------------------------------------------------
// Kernel 2: persistent LSTM, 125 blocks x 512 threads, fp16 m16n8k16 MMA.
//   NO global step barrier: chunk ch of A depends only on producer blocks
//   16ch..16ch+15 (13 for ch=7); each warp waits on exactly those slots
//   (acquire) right before prefetching that chunk, overlapping stragglers
//   with MMA on earlier chunks. Publish = syncthreads + single release store.
// ---------------------------------------------------------------------------
#define WS_STRIDE 516               // half2 words; 516 % 32 == 4 -> conflict-free
#define W_WORDS (32 * WS_STRIDE)
#define RED_STRIDE 36               // words; 36%32==4 (conflict-free) AND 16B-aligned
#define SMEM_WORDS (W_WORDS + 512 * RED_STRIDE)

__global__ void __launch_bounds__(512, 1) lstm_persistent(
    const float* __restrict__ c0, const float* __restrict__ Whh,
    float* __restrict__ out)
{
    extern __shared__ unsigned sm[];
    unsigned* W_s = sm;                         // [32][516] packed half2
    float*    red = (float*)(sm + W_WORDS);     // [512][36]

    const int bid  = blockIdx.x;
    const int j0   = bid * 8;
    const int tid  = threadIdx.x;
    const int lane = tid & 31;
    const int warp = tid >> 5;
    const int wk = warp & 7;        // k16 slice within each k128 chunk
    const int wm = warp >> 3;       // m-half (32 batch rows)
    const int g_id = lane >> 2;
    const int t_id = lane & 3;

    // ---- resident W: 32 gate-major rows x 512 half2 (zero-padded) ----
    for (int idx = tid; idx < 32 * 512; idx += 512) {
        int n = idx >> 9, k2 = idx & 511;
        int row = (n >> 3) * HH + j0 + (n & 7);
        int k = k2 * 2;
        float v0 = (k < HH)     ? Whh[(size_t)row * HH + k]     : 0.0f;
        float v1 = (k + 1 < HH) ? Whh[(size_t)row * HH + k + 1] : 0.0f;
        __half2 hv = __floats2half2_rn(v0, v1);
        W_s[n * WS_STRIDE + k2] = *(unsigned*)&hv;
    }

    // ---- per-thread cell state + xg prefetch (1 cell: b=tid>>3, jj=tid&7) ----
    const int eb = tid >> 3, ej = tid & 7;
    float c_reg = c0[eb * HH + j0 + ej];
    float xg[4];
    {
        const float* p = g_xg + (size_t)eb * G4 + j0 + ej;
#pragma unroll
        for (int g = 0; g < 4; ++g) xg[g] = p[g * HH];
    }
    const int scat = frag_half_of(eb, j0 + ej);   // epilogue scatter (half index)
    __syncthreads();

    // per-warp fragment base: uint4 index = (((wm*8+wk)*8+ch)*2+mt)*32 + lane
    const int fvec = ((wm * 8 + wk) * 8) * 2 * 32 + lane;

    // per-warp chunk wait: slots of the 16 (13 for ch=7) producer blocks
    const unsigned* myslot0 = &g_slot[lane & 15];
    auto chunk_wait = [&](int ch, unsigned tgt) {
        const int cnt = (ch == 7) ? 13 : 16;
        const unsigned* sp = myslot0 + ch * 16;
        const bool mine = (lane & 15) < cnt;
        for (;;) {
            bool ok = true;
            if (mine) ok = (ld_acq(sp) >= tgt);
            if (__ballot_sync(0xffffffffu, ok) == 0xffffffffu) break;
        }
    };

    for (int t = 0; t < TT; ++t) {
        const uint4* Af = (const uint4*)g_hf[t & 1];
        const unsigned tgt = (unsigned)t;

        float acc[2][4][4];
#pragma unroll
        for (int mt = 0; mt < 2; ++mt)
#pragma unroll
            for (int nt = 0; nt < 4; ++nt)
#pragma unroll
                for (int i = 0; i < 4; ++i) acc[mt][nt][i] = 0.0f;

        // ---- K loop: 8 chunks; per-chunk producer wait + LDG.128 prefetch --
        uint4 av[2][2];   // [buf][mt]
        if (t > 0) chunk_wait(0, tgt);
        av[0][0] = Af[fvec];
        av[0][1] = Af[fvec + 32];
#pragma unroll
        for (int ch = 0; ch < 8; ++ch) {
            if (ch < 7) {
                if (t > 0) chunk_wait(ch + 1, tgt);
                av[(ch + 1) & 1][0] = Af[fvec + (ch + 1) * 64];
                av[(ch + 1) & 1][1] = Af[fvec + (ch + 1) * 64 + 32];
            }
            const uint4* a = av[ch & 1];
            const int kg2 = ch * 64 + wk * 8;   // half2-word offset in W_s row
#pragma unroll
            for (int nt = 0; nt < 4; ++nt) {
                unsigned b0 = W_s[(nt * 8 + g_id) * WS_STRIDE + kg2 + t_id];
                unsigned b1 = W_s[(nt * 8 + g_id) * WS_STRIDE + kg2 + t_id + 4];
                mma_f16(acc[0][nt], a[0].x, a[0].y, a[0].z, a[0].w, b0, b1);
                mma_f16(acc[1][nt], a[1].x, a[1].y, a[1].z, a[1].w, b0, b1);
            }
        }

        // ---- dump partials (float4 STS, 16B-aligned stride) ----
        {
            float* my = red + (size_t)tid * RED_STRIDE;
#pragma unroll
            for (int mt = 0; mt < 2; ++mt)
#pragma unroll
                for (int nt = 0; nt < 4; ++nt)
                    *(float4*)&my[(mt * 4 + nt) * 4] =
                        make_float4(acc[mt][nt][0], acc[mt][nt][1],
                                    acc[mt][nt][2], acc[mt][nt][3]);
        }
        __syncthreads();

        // ---- 8-way K reduction + fused cell update (1 cell/thread) ----
        {
            const int wmh   = eb >> 5;
            const int mt    = (eb >> 4) & 1;
            const int lane_ = (eb & 7) * 4 + (ej >> 1);
            const int v     = ((eb >> 3) & 1) * 2 + (ej & 1);
            float gv[4];
#pragma unroll
            for (int g = 0; g < 4; ++g) {
                const int i = (mt * 4 + g) * 4 + v;
                float s = 0.0f;
#pragma unroll
                for (int k = 0; k < 8; ++k)
                    s += red[(size_t)((wmh * 8 + k) * 32 + lane_) * RED_STRIDE + i];
                gv[g] = s + xg[g];
            }
            float iv = sigmoidf_(gv[0]);
            float fv = sigmoidf_(gv[1]);
            float gg = tanhf_(gv[2]);
            float ov = sigmoidf_(gv[3]);
            float cn = fv * c_reg + iv * gg;
            c_reg = cn;
            float hn = ov * tanhf_(cn);
            out[((size_t)t * BB + eb) * HH + j0 + ej] = hn;
            g_hf[(t + 1) & 1][scat] = __float2half_rn(hn);
        }

        // ---- publish: intra-block order via syncthreads, then release store --
        __syncthreads();
        if (tid == 0) st_rel(&g_slot[bid], (unsigned)(t + 1));

        // ---- prefetch x_gates for t+1 ----
        if (t + 1 < TT) {
            const float* p = g_xg + ((size_t)(t + 1) * BB + eb) * G4 + j0 + ej;
#pragma unroll
            for (int g = 0; g < 4; ++g) xg[g] = p[g * HH];
        }
    }
}

// ---------------------------------------------------------------------------
// Launch
// ---------------------------------------------------------------------------
extern "C" void kernel_launch(void* const* d_in, const int* in_sizes, int n_in,
                              void* d_out, int out_size) {
    const float* inputs = (const float*)d_in[0];
    const float* h0     = (const float*)d_in[1];
    const float* c0     = (const float*)d_in[2];
    const float* W_ih   = (const float*)d_in[3];
    const float* W_hh   = (const float*)d_in[4];
    const float* b_ih   = (const float*)d_in[5];
    const float* b_hh   = (const float*)d_in[6];
    float* out = (float*)d_out;

    cudaFuncSetAttribute(lstm_persistent,
                         cudaFuncAttributeMaxDynamicSharedMemorySize,
                         SMEM_WORDS * 4);

    xgates_kernel<<<dim3(63, 513), 256>>>(inputs, W_ih, b_ih, b_hh, h0);
    lstm_persistent<<<NBLK, 512, SMEM_WORDS * 4>>>(c0, W_hh, out);
}

// round 16
// speedup vs baseline: 1.0482x; 1.0482x over previous
#include <cuda_runtime.h>
#include <cuda_fp16.h>
#include <cstdint>
#include <math.h>

// Problem constants
#define TT 512
#define BB 64
#define II 300
#define HH 1000
#define G4 4000
#define KP 1024           // padded K
#define NBLK 125          // persistent blocks (<=148 SMs -> co-resident)

// ---------------------------------------------------------------------------
// Device scratch (allocation-free: __device__ globals)
// ---------------------------------------------------------------------------
__device__ float g_xg[(size_t)TT * BB * G4];   // x_gates [T,B,4H]
__device__ __half g_hf[2][BB * KP];            // h as fp16 MMA fragments, 2 parities
__device__ unsigned g_slot[128];               // per-block step slots

// ---------------------------------------------------------------------------
// helpers
// ---------------------------------------------------------------------------
__device__ __forceinline__ unsigned f2tf32(float x) {
    unsigned y;
    asm("cvt.rna.tf32.f32 %0, %1;" : "=r"(y) : "f"(x));
    return y;
}
__device__ __forceinline__ void mma_tf32(float c[4], unsigned a0, unsigned a1,
                                         unsigned a2, unsigned a3,
                                         unsigned b0, unsigned b1) {
    asm volatile(
        "mma.sync.aligned.m16n8k8.row.col.f32.tf32.tf32.f32 "
        "{%0,%1,%2,%3}, {%4,%5,%6,%7}, {%8,%9}, {%0,%1,%2,%3};"
        : "+f"(c[0]), "+f"(c[1]), "+f"(c[2]), "+f"(c[3])
        : "r"(a0), "r"(a1), "r"(a2), "r"(a3), "r"(b0), "r"(b1));
}
__device__ __forceinline__ void mma_f16(float c[4], unsigned a0, unsigned a1,
                                        unsigned a2, unsigned a3,
                                        unsigned b0, unsigned b1) {
    asm volatile(
        "mma.sync.aligned.m16n8k16.row.col.f32.f16.f16.f32 "
        "{%0,%1,%2,%3}, {%4,%5,%6,%7}, {%8,%9}, {%0,%1,%2,%3};"
        : "+f"(c[0]), "+f"(c[1]), "+f"(c[2]), "+f"(c[3])
        : "r"(a0), "r"(a1), "r"(a2), "r"(a3), "r"(b0), "r"(b1));
}
__device__ __forceinline__ float sigmoidf_(float x) { return 1.0f / (1.0f + __expf(-x)); }
__device__ __forceinline__ float tanhf_(float x) { return 2.0f / (1.0f + __expf(-2.0f * x)) - 1.0f; }

// fp16 fragment half-index of A element (b, kglob), warp tile m16 x k16:
//   warp wm = b>>4 owns rows [wm*16, +16); kc = kglob>>4 is the k16 index.
//   Within fragment (validated mapping from R13): row r = g + 8*rsel,
//   k l = 2*(tq + 4*ksel) + lo; lane = g*4+tq; regs a0..a3 = ksel*2+rsel.
__device__ __forceinline__ int frag_half_of(int b, int kglob) {
    int wm = b >> 4, r = b & 15, g = r & 7, rsel = r >> 3;
    int kc = kglob >> 4, kl = kglob & 15;
    int p = kl >> 1, lo = kl & 1, tq = p & 3, ksel = p >> 2;
    int lane = g * 4 + tq;
    int reg  = ksel * 2 + rsel;
    int word = ((wm * 64 + kc) * 32 + lane) * 4 + reg;
    return word * 2 + lo;
}

// ---------------------------------------------------------------------------
// Kernel 1: x_gates GEMM (tf32)  +  prep row (y==512):
//           h0 -> g_hf[0] fp16 fragments, slot reset.
// ---------------------------------------------------------------------------
__global__ void __launch_bounds__(256) xgates_kernel(
    const float* __restrict__ X, const float* __restrict__ Wih,
    const float* __restrict__ b_ih, const float* __restrict__ b_hh,
    const float* __restrict__ h0)
{
    if (blockIdx.y == 512) {               // prep row: 63 blocks
        const int bx = blockIdx.x;
        if (bx == 0 && threadIdx.x < 128) g_slot[threadIdx.x] = 0u;
        for (int b = bx; b < BB; b += 63) {
            for (int k = threadIdx.x; k < HH; k += 256)
                g_hf[0][frag_half_of(b, k)] = __float2half_rn(h0[b * HH + k]);
        }
        return;
    }

    const int m0 = blockIdx.y * 64;
    const int n0 = blockIdx.x * 64;
    const int tid  = threadIdx.x;
    const int lane = tid & 31;
    const int warp = tid >> 5;
    const int wm = warp & 3;
    const int wn = warp >> 2;

    __shared__ unsigned a_s[64][17];
    __shared__ unsigned b_s[64][17];

    float acc[4][4];
#pragma unroll
    for (int s = 0; s < 4; ++s)
#pragma unroll
        for (int i = 0; i < 4; ++i) acc[s][i] = 0.0f;

    const int g_id = lane >> 2;
    const int t_id = lane & 3;

    for (int ch = 0; ch < 19; ++ch) {
        const int k0 = ch * 16;
#pragma unroll
        for (int it = 0; it < 4; ++it) {
            int i = tid + it * 256;
            int m = i >> 4, k = i & 15;
            float va = (k0 + k < II) ? X[(size_t)(m0 + m) * II + k0 + k] : 0.0f;
            a_s[m][k] = f2tf32(va);
            int r = n0 + m;
            float vb = (r < G4 && k0 + k < II) ? Wih[(size_t)r * II + k0 + k] : 0.0f;
            b_s[m][k] = f2tf32(vb);
        }
        __syncthreads();

#pragma unroll
        for (int kk = 0; kk < 2; ++kk) {
            const int kb = kk * 8;
            unsigned a[4];
            a[0] = a_s[wm * 16 + g_id][kb + t_id];
            a[1] = a_s[wm * 16 + g_id + 8][kb + t_id];
            a[2] = a_s[wm * 16 + g_id][kb + t_id + 4];
            a[3] = a_s[wm * 16 + g_id + 8][kb + t_id + 4];
#pragma unroll
            for (int s = 0; s < 4; ++s) {
                unsigned b0 = b_s[wn * 32 + s * 8 + g_id][kb + t_id];
                unsigned b1 = b_s[wn * 32 + s * 8 + g_id][kb + t_id + 4];
                mma_tf32(acc[s], a[0], a[1], a[2], a[3], b0, b1);
            }
        }
        __syncthreads();
    }

#pragma unroll
    for (int s = 0; s < 4; ++s) {
        int n = n0 + wn * 32 + s * 8 + 2 * t_id;
        int row = m0 + wm * 16 + g_id;
        if (n < G4) {
            float bia0 = b_ih[n] + b_hh[n];
            float bia1 = b_ih[n + 1] + b_hh[n + 1];
            g_xg[(size_t)row * G4 + n]           = acc[s][0] + bia0;
            g_xg[(size_t)row * G4 + n + 1]       = acc[s][1] + bia1;
            g_xg[(size_t)(row + 8) * G4 + n]     = acc[s][2] + bia0;
            g_xg[(size_t)(row + 8) * G4 + n + 1] = acc[s][3] + bia1;
        }
    }
}

// ---------------------------------------------------------------------------
// Kernel 2: persistent LSTM, 125 blocks x 512 threads, fp16 m16n8k16 MMA.
//   Warp tile = m16 x n8 (one gate) x FULL K=1024: accumulator is the final
//   gate value -> NO cross-warp K reduction. Small g_sm exchange (8 KB) +
//   fused cell update. A read directly from fragment-ordered g_hf[t&1] via
//   LDG.128 (prefetch depth 4). Global slot barrier identical to R13.
// ---------------------------------------------------------------------------
#define WS_STRIDE 516               // half2 words; 516 % 32 == 4 -> conflict-free
#define W_WORDS (32 * WS_STRIDE)
#define GS_STRIDE 33
#define SMEM_WORDS (W_WORDS + 64 * GS_STRIDE)

__global__ void __launch_bounds__(512, 1) lstm_persistent(
    const float* __restrict__ c0, const float* __restrict__ Whh,
    float* __restrict__ out)
{
    extern __shared__ unsigned sm[];
    unsigned* W_s  = sm;                        // [32][516] packed half2
    float*    g_sm = (float*)(sm + W_WORDS);    // [64][33] gate exchange

    const int bid  = blockIdx.x;
    const int j0   = bid * 8;
    const int tid  = threadIdx.x;
    const int lane = tid & 31;
    const int warp = tid >> 5;
    const int wm = warp & 3;        // m-tile: batch rows wm*16 .. +15
    const int wn = warp >> 2;       // n-tile: gate wn, cols wn*8 .. +7
    const int g_id = lane >> 2;
    const int t_id = lane & 3;

    // ---- resident W: 32 gate-major rows x 512 half2 (zero-padded) ----
    for (int idx = tid; idx < 32 * 512; idx += 512) {
        int n = idx >> 9, k2 = idx & 511;
        int row = (n >> 3) * HH + j0 + (n & 7);
        int k = k2 * 2;
        float v0 = (k < HH)     ? Whh[(size_t)row * HH + k]     : 0.0f;
        float v1 = (k + 1 < HH) ? Whh[(size_t)row * HH + k + 1] : 0.0f;
        __half2 hv = __floats2half2_rn(v0, v1);
        W_s[n * WS_STRIDE + k2] = *(unsigned*)&hv;
    }

    // ---- per-thread cell state + xg prefetch (1 cell: b=tid>>3, jj=tid&7) ----
    const int eb = tid >> 3, ej = tid & 7;
    float c_reg = c0[eb * HH + j0 + ej];
    float xg[4];
    {
        const float* p = g_xg + (size_t)eb * G4 + j0 + ej;
#pragma unroll
        for (int g = 0; g < 4; ++g) xg[g] = p[g * HH];
    }
    const int scat = frag_half_of(eb, j0 + ej);   // epilogue scatter (half index)
    __syncthreads();

    // per-warp A fragment base: uint4 index = (wm*64 + kc)*32 + lane
    const int fvec = wm * 64 * 32 + lane;
    // per-warp B row base in W_s (half2 words)
    const int brow = (wn * 8 + g_id) * WS_STRIDE;

    for (int t = 0; t < TT; ++t) {
        // ---- global slot barrier (R13-proven): wait for h_{t-1} ----
        if (t > 0) {
            if (warp == 0) {
                const unsigned tgt = (unsigned)t;
                for (;;) {
                    bool ok = true;
#pragma unroll
                    for (int s = 0; s < 4; ++s) {
                        int id = lane + 32 * s;
                        if (id < NBLK) ok &= (*(volatile unsigned*)&g_slot[id] >= tgt);
                    }
                    if (__ballot_sync(0xffffffffu, ok) == 0xffffffffu) break;
                }
                __threadfence();
            }
            __syncthreads();
        }
        const uint4* Af = (const uint4*)g_hf[t & 1];

        float acc[4] = {0.0f, 0.0f, 0.0f, 0.0f};

        // ---- K loop: 64 k16 steps, A prefetch depth 4 ----
        uint4 av[4];
#pragma unroll
        for (int i = 0; i < 4; ++i) av[i] = Af[fvec + i * 32];
#pragma unroll 4
        for (int kc = 0; kc < 64; ++kc) {
            uint4 a = av[kc & 3];
            if (kc + 4 < 64) av[kc & 3] = Af[fvec + (kc + 4) * 32];
            unsigned b0 = W_s[brow + kc * 8 + t_id];
            unsigned b1 = W_s[brow + kc * 8 + t_id + 4];
            mma_f16(acc, a.x, a.y, a.z, a.w, b0, b1);
        }

        // ---- exchange: acc -> g_sm[b][gate*8 + jj] ----
        {
            const int row = wm * 16 + g_id;
            const int col = wn * 8 + 2 * t_id;
            g_sm[row * GS_STRIDE + col]           = acc[0];
            g_sm[row * GS_STRIDE + col + 1]       = acc[1];
            g_sm[(row + 8) * GS_STRIDE + col]     = acc[2];
            g_sm[(row + 8) * GS_STRIDE + col + 1] = acc[3];
        }
        __syncthreads();

        // ---- fused cell update (1 cell/thread) ----
        {
            float iv = g_sm[eb * GS_STRIDE + ej]       + xg[0];
            float fv = g_sm[eb * GS_STRIDE + 8 + ej]   + xg[1];
            float gg = g_sm[eb * GS_STRIDE + 16 + ej]  + xg[2];
            float ov = g_sm[eb * GS_STRIDE + 24 + ej]  + xg[3];
            iv = sigmoidf_(iv);
            fv = sigmoidf_(fv);
            gg = tanhf_(gg);
            ov = sigmoidf_(ov);
            float cn = fv * c_reg + iv * gg;
            c_reg = cn;
            float hn = ov * tanhf_(cn);
            out[((size_t)t * BB + eb) * HH + j0 + ej] = hn;
            g_hf[(t + 1) & 1][scat] = __float2half_rn(hn);
        }

        // ---- publish (R13-proven): fence, sync, slot store ----
        __threadfence();
        __syncthreads();
        if (tid == 0) *(volatile unsigned*)&g_slot[bid] = (unsigned)(t + 1);

        // ---- prefetch x_gates for t+1 ----
        if (t + 1 < TT) {
            const float* p = g_xg + ((size_t)(t + 1) * BB + eb) * G4 + j0 + ej;
#pragma unroll
            for (int g = 0; g < 4; ++g) xg[g] = p[g * HH];
        }
    }
}

// ---------------------------------------------------------------------------
// Launch
// ---------------------------------------------------------------------------
extern "C" void kernel_launch(void* const* d_in, const int* in_sizes, int n_in,
                              void* d_out, int out_size) {
    const float* inputs = (const float*)d_in[0];
    const float* h0     = (const float*)d_in[1];
    const float* c0     = (const float*)d_in[2];
    const float* W_ih   = (const float*)d_in[3];
    const float* W_hh   = (const float*)d_in[4];
    const float* b_ih   = (const float*)d_in[5];
    const float* b_hh   = (const float*)d_in[6];
    float* out = (float*)d_out;

    cudaFuncSetAttribute(lstm_persistent,
                         cudaFuncAttributeMaxDynamicSharedMemorySize,
                         SMEM_WORDS * 4);

    xgates_kernel<<<dim3(63, 513), 256>>>(inputs, W_ih, b_ih, b_hh, h0);
    lstm_persistent<<<NBLK, 512, SMEM_WORDS * 4>>>(c0, W_hh, out);
}

// round 17
// speedup vs baseline: 1.1821x; 1.1277x over previous
#include <cuda_runtime.h>
#include <cuda_fp16.h>
#include <cstdint>
#include <math.h>

// Problem constants
#define TT 512
#define BB 64
#define II 300
#define HH 1000
#define G4 4000
#define KP 1024           // padded K
#define NBLK 125          // persistent blocks (<=148 SMs -> co-resident)

// ---------------------------------------------------------------------------
// Device scratch (allocation-free: __device__ globals)
// ---------------------------------------------------------------------------
__device__ float g_xg[(size_t)TT * BB * G4];   // x_gates [T,B,4H]
__device__ __half g_hf[2][BB * KP];            // h as fp16 MMA fragments, 2 parities
__device__ unsigned g_slot[128];               // per-block step slots

// ---------------------------------------------------------------------------
// helpers
// ---------------------------------------------------------------------------
__device__ __forceinline__ unsigned f2tf32(float x) {
    unsigned y;
    asm("cvt.rna.tf32.f32 %0, %1;" : "=r"(y) : "f"(x));
    return y;
}
__device__ __forceinline__ void mma_tf32(float c[4], unsigned a0, unsigned a1,
                                         unsigned a2, unsigned a3,
                                         unsigned b0, unsigned b1) {
    asm volatile(
        "mma.sync.aligned.m16n8k8.row.col.f32.tf32.tf32.f32 "
        "{%0,%1,%2,%3}, {%4,%5,%6,%7}, {%8,%9}, {%0,%1,%2,%3};"
        : "+f"(c[0]), "+f"(c[1]), "+f"(c[2]), "+f"(c[3])
        : "r"(a0), "r"(a1), "r"(a2), "r"(a3), "r"(b0), "r"(b1));
}
__device__ __forceinline__ void mma_f16(float c[4], unsigned a0, unsigned a1,
                                        unsigned a2, unsigned a3,
                                        unsigned b0, unsigned b1) {
    asm volatile(
        "mma.sync.aligned.m16n8k16.row.col.f32.f16.f16.f32 "
        "{%0,%1,%2,%3}, {%4,%5,%6,%7}, {%8,%9}, {%0,%1,%2,%3};"
        : "+f"(c[0]), "+f"(c[1]), "+f"(c[2]), "+f"(c[3])
        : "r"(a0), "r"(a1), "r"(a2), "r"(a3), "r"(b0), "r"(b1));
}
__device__ __forceinline__ float sigmoidf_(float x) { return 1.0f / (1.0f + __expf(-x)); }
__device__ __forceinline__ float tanhf_(float x) { return 2.0f / (1.0f + __expf(-2.0f * x)) - 1.0f; }

__device__ __forceinline__ unsigned ld_acq(const unsigned* p) {
    unsigned v;
    asm volatile("ld.acquire.gpu.global.u32 %0, [%1];" : "=r"(v) : "l"(p) : "memory");
    return v;
}
__device__ __forceinline__ void st_rel(unsigned* p, unsigned v) {
    asm volatile("st.release.gpu.global.u32 [%0], %1;" :: "l"(p), "r"(v) : "memory");
}

// fp16 fragment half-index of A element (b, kglob) for m16n8k16.row
// (R13-validated mapping; warp grid wk=8 x wm=2, 8 chunks of k128):
__device__ __forceinline__ int frag_half_of(int b, int kglob) {
    int wm = b >> 5, mt = (b >> 4) & 1, r = b & 15, g = r & 7, rsel = r >> 3;
    int ch = kglob >> 7, kr = kglob & 127;
    int wk = kr >> 4, kl = kr & 15;
    int p = kl >> 1, lo = kl & 1, tq = p & 3, ksel = p >> 2;
    int lane = g * 4 + tq;
    int reg  = ksel * 2 + rsel;
    int word = ((((wm * 8 + wk) * 8 + ch) * 2 + mt) * 32 + lane) * 4 + reg;
    return word * 2 + lo;
}

// ---------------------------------------------------------------------------
// Kernel 1: x_gates GEMM (tf32)  +  prep row (y==512):
//           h0 -> g_hf[0] fp16 fragments, slot reset.
// ---------------------------------------------------------------------------
__global__ void __launch_bounds__(256) xgates_kernel(
    const float* __restrict__ X, const float* __restrict__ Wih,
    const float* __restrict__ b_ih, const float* __restrict__ b_hh,
    const float* __restrict__ h0)
{
    if (blockIdx.y == 512) {               // prep row: 63 blocks
        const int bx = blockIdx.x;
        if (bx == 0 && threadIdx.x < 128) g_slot[threadIdx.x] = 0u;
        for (int b = bx; b < BB; b += 63) {
            for (int k = threadIdx.x; k < HH; k += 256)
                g_hf[0][frag_half_of(b, k)] = __float2half_rn(h0[b * HH + k]);
        }
        return;
    }

    const int m0 = blockIdx.y * 64;
    const int n0 = blockIdx.x * 64;
    const int tid  = threadIdx.x;
    const int lane = tid & 31;
    const int warp = tid >> 5;
    const int wm = warp & 3;
    const int wn = warp >> 2;

    __shared__ unsigned a_s[64][17];
    __shared__ unsigned b_s[64][17];

    float acc[4][4];
#pragma unroll
    for (int s = 0; s < 4; ++s)
#pragma unroll
        for (int i = 0; i < 4; ++i) acc[s][i] = 0.0f;

    const int g_id = lane >> 2;
    const int t_id = lane & 3;

    for (int ch = 0; ch < 19; ++ch) {
        const int k0 = ch * 16;
#pragma unroll
        for (int it = 0; it < 4; ++it) {
            int i = tid + it * 256;
            int m = i >> 4, k = i & 15;
            float va = (k0 + k < II) ? X[(size_t)(m0 + m) * II + k0 + k] : 0.0f;
            a_s[m][k] = f2tf32(va);
            int r = n0 + m;
            float vb = (r < G4 && k0 + k < II) ? Wih[(size_t)r * II + k0 + k] : 0.0f;
            b_s[m][k] = f2tf32(vb);
        }
        __syncthreads();

#pragma unroll
        for (int kk = 0; kk < 2; ++kk) {
            const int kb = kk * 8;
            unsigned a[4];
            a[0] = a_s[wm * 16 + g_id][kb + t_id];
            a[1] = a_s[wm * 16 + g_id + 8][kb + t_id];
            a[2] = a_s[wm * 16 + g_id][kb + t_id + 4];
            a[3] = a_s[wm * 16 + g_id + 8][kb + t_id + 4];
#pragma unroll
            for (int s = 0; s < 4; ++s) {
                unsigned b0 = b_s[wn * 32 + s * 8 + g_id][kb + t_id];
                unsigned b1 = b_s[wn * 32 + s * 8 + g_id][kb + t_id + 4];
                mma_tf32(acc[s], a[0], a[1], a[2], a[3], b0, b1);
            }
        }
        __syncthreads();
    }

#pragma unroll
    for (int s = 0; s < 4; ++s) {
        int n = n0 + wn * 32 + s * 8 + 2 * t_id;
        int row = m0 + wm * 16 + g_id;
        if (n < G4) {
            float bia0 = b_ih[n] + b_hh[n];
            float bia1 = b_ih[n + 1] + b_hh[n + 1];
            g_xg[(size_t)row * G4 + n]           = acc[s][0] + bia0;
            g_xg[(size_t)row * G4 + n + 1]       = acc[s][1] + bia1;
            g_xg[(size_t)(row + 8) * G4 + n]     = acc[s][2] + bia0;
            g_xg[(size_t)(row + 8) * G4 + n + 1] = acc[s][3] + bia1;
        }
    }
}

// ---------------------------------------------------------------------------
// Kernel 2: persistent LSTM, 125 blocks x 512 threads, fp16 m16n8k16 MMA.
//   R13-proven structure: warp (wk=warp&7, wm=warp>>3) = m32 x n32 x k16 slice
//   of each of 8 chunks (8 independent acc chains), global slot barrier,
//   8-way K reduction, fused cell update. R17 delta: release/acquire publish
//   (no block-wide threadfence) + out-store moved off the publish path.
// ---------------------------------------------------------------------------
#define WS_STRIDE 516               // half2 words; 516 % 32 == 4 -> conflict-free
#define W_WORDS (32 * WS_STRIDE)
#define RED_STRIDE 33
#define SMEM_WORDS (W_WORDS + 512 * RED_STRIDE)

__global__ void __launch_bounds__(512, 1) lstm_persistent(
    const float* __restrict__ c0, const float* __restrict__ Whh,
    float* __restrict__ out)
{
    extern __shared__ unsigned sm[];
    unsigned* W_s = sm;                         // [32][516] packed half2
    float*    red = (float*)(sm + W_WORDS);     // [512][33]

    const int bid  = blockIdx.x;
    const int j0   = bid * 8;
    const int tid  = threadIdx.x;
    const int lane = tid & 31;
    const int warp = tid >> 5;
    const int wk = warp & 7;        // k16 slice within each k128 chunk
    const int wm = warp >> 3;       // m-half (32 batch rows)
    const int g_id = lane >> 2;
    const int t_id = lane & 3;

    // ---- resident W: 32 gate-major rows x 512 half2 (zero-padded) ----
    for (int idx = tid; idx < 32 * 512; idx += 512) {
        int n = idx >> 9, k2 = idx & 511;
        int row = (n >> 3) * HH + j0 + (n & 7);
        int k = k2 * 2;
        float v0 = (k < HH)     ? Whh[(size_t)row * HH + k]     : 0.0f;
        float v1 = (k + 1 < HH) ? Whh[(size_t)row * HH + k + 1] : 0.0f;
        __half2 hv = __floats2half2_rn(v0, v1);
        W_s[n * WS_STRIDE + k2] = *(unsigned*)&hv;
    }

    // ---- per-thread cell state + xg prefetch (1 cell: b=tid>>3, jj=tid&7) ----
    const int eb = tid >> 3, ej = tid & 7;
    float c_reg = c0[eb * HH + j0 + ej];
    float xg[4];
    {
        const float* p = g_xg + (size_t)eb * G4 + j0 + ej;
#pragma unroll
        for (int g = 0; g < 4; ++g) xg[g] = p[g * HH];
    }
    const int scat = frag_half_of(eb, j0 + ej);   // epilogue scatter (half index)
    __syncthreads();

    // per-warp fragment base: uint4 index = (((wm*8+wk)*8+ch)*2+mt)*32 + lane
    const int fvec = ((wm * 8 + wk) * 8) * 2 * 32 + lane;

    for (int t = 0; t < TT; ++t) {
        // ---- slot barrier: warp 0 polls all 125 slots with acquire loads ----
        if (t > 0) {
            if (warp == 0) {
                const unsigned tgt = (unsigned)t;
                for (;;) {
                    bool ok = true;
#pragma unroll
                    for (int s = 0; s < 4; ++s) {
                        int id = lane + 32 * s;
                        if (id < NBLK) ok &= (ld_acq(&g_slot[id]) >= tgt);
                    }
                    if (__ballot_sync(0xffffffffu, ok) == 0xffffffffu) break;
                }
            }
            __syncthreads();
        }
        const uint4* Af = (const uint4*)g_hf[t & 1];

        float acc[2][4][4];
#pragma unroll
        for (int mt = 0; mt < 2; ++mt)
#pragma unroll
            for (int nt = 0; nt < 4; ++nt)
#pragma unroll
                for (int i = 0; i < 4; ++i) acc[mt][nt][i] = 0.0f;

        // ---- K loop: 8 chunks; A via direct LDG.128, double-buffered ----
        uint4 av[2][2];   // [buf][mt]
        av[0][0] = Af[fvec];
        av[0][1] = Af[fvec + 32];
#pragma unroll
        for (int ch = 0; ch < 8; ++ch) {
            if (ch < 7) {
                av[(ch + 1) & 1][0] = Af[fvec + (ch + 1) * 64];
                av[(ch + 1) & 1][1] = Af[fvec + (ch + 1) * 64 + 32];
            }
            const uint4* a = av[ch & 1];
            const int kg2 = ch * 64 + wk * 8;   // half2-word offset in W_s row
#pragma unroll
            for (int nt = 0; nt < 4; ++nt) {
                unsigned b0 = W_s[(nt * 8 + g_id) * WS_STRIDE + kg2 + t_id];
                unsigned b1 = W_s[(nt * 8 + g_id) * WS_STRIDE + kg2 + t_id + 4];
                mma_f16(acc[0][nt], a[0].x, a[0].y, a[0].z, a[0].w, b0, b1);
                mma_f16(acc[1][nt], a[1].x, a[1].y, a[1].z, a[1].w, b0, b1);
            }
        }

        // ---- dump partials (scalar STS, R13 layout) ----
        {
            float* my = red + (size_t)tid * RED_STRIDE;
#pragma unroll
            for (int mt = 0; mt < 2; ++mt)
#pragma unroll
                for (int nt = 0; nt < 4; ++nt)
#pragma unroll
                    for (int v = 0; v < 4; ++v)
                        my[(mt * 4 + nt) * 4 + v] = acc[mt][nt][v];
        }
        __syncthreads();

        // ---- 8-way K reduction + fused cell update (1 cell/thread) ----
        float hn;
        {
            const int wmh   = eb >> 5;
            const int mt    = (eb >> 4) & 1;
            const int lane_ = (eb & 7) * 4 + (ej >> 1);
            const int v     = ((eb >> 3) & 1) * 2 + (ej & 1);
            float gv[4];
#pragma unroll
            for (int g = 0; g < 4; ++g) {
                const int i = (mt * 4 + g) * 4 + v;
                float s = 0.0f;
#pragma unroll
                for (int k = 0; k < 8; ++k)
                    s += red[(size_t)((wmh * 8 + k) * 32 + lane_) * RED_STRIDE + i];
                gv[g] = s + xg[g];
            }
            float iv = sigmoidf_(gv[0]);
            float fv = sigmoidf_(gv[1]);
            float gg = tanhf_(gv[2]);
            float ov = sigmoidf_(gv[3]);
            float cn = fv * c_reg + iv * gg;
            c_reg = cn;
            hn = ov * tanhf_(cn);
            // publish-critical store FIRST: fragments for t+1
            g_hf[(t + 1) & 1][scat] = __float2half_rn(hn);
        }

        // ---- publish: syncthreads (intra-block HB) + one release store ----
        __syncthreads();
        if (tid == 0) st_rel(&g_slot[bid], (unsigned)(t + 1));

        // ---- off the publish path: out store + x_gates prefetch ----
        out[((size_t)t * BB + eb) * HH + j0 + ej] = hn;
        if (t + 1 < TT) {
            const float* p = g_xg + ((size_t)(t + 1) * BB + eb) * G4 + j0 + ej;
#pragma unroll
            for (int g = 0; g < 4; ++g) xg[g] = p[g * HH];
        }
    }
}

// ---------------------------------------------------------------------------
// Launch
// ---------------------------------------------------------------------------
extern "C" void kernel_launch(void* const* d_in, const int* in_sizes, int n_in,
                              void* d_out, int out_size) {
    const float* inputs = (const float*)d_in[0];
    const float* h0     = (const float*)d_in[1];
    const float* c0     = (const float*)d_in[2];
    const float* W_ih   = (const float*)d_in[3];
    const float* W_hh   = (const float*)d_in[4];
    const float* b_ih   = (const float*)d_in[5];
    const float* b_hh   = (const float*)d_in[6];
    float* out = (float*)d_out;

    cudaFuncSetAttribute(lstm_persistent,
                         cudaFuncAttributeMaxDynamicSharedMemorySize,
                         SMEM_WORDS * 4);

    xgates_kernel<<<dim3(63, 513), 256>>>(inputs, W_ih, b_ih, b_hh, h0);
    lstm_persistent<<<NBLK, 512, SMEM_WORDS * 4>>>(c0, W_hh, out);
}